// round 5
// baseline (speedup 1.0000x reference)
#include <cuda_runtime.h>
#include <cstdint>

#define S_LEN   4096
#define BATCH   4
#define D_MODEL 512
#define DHEAD   64
#define BSROWS  (BATCH * S_LEN)

// Scratch (allocation-free rule: __device__ globals)
__device__ float g_q[BSROWS * DHEAD];     // tf32 bits
__device__ float g_k[BSROWS * DHEAD];     // tf32 bits
__device__ float g_v[BSROWS * DHEAD];     // tf32 bits
__device__ float g_attn[BSROWS * DHEAD];  // tf32 bits
__device__ float g_w[D_MODEL * 192];      // Wq|Wk|Wv merged, tf32 bits
__device__ float g_wo[DHEAD * D_MODEL];   // Wo, tf32 bits

__device__ __forceinline__ float ex2f(float x) {
    float y; asm("ex2.approx.f32 %0, %1;" : "=f"(y) : "f"(x)); return y;
}
__device__ __forceinline__ uint32_t f2tf(float x) {
    uint32_t r; asm("cvt.rna.tf32.f32 %0, %1;" : "=r"(r) : "f"(x)); return r;
}
__device__ __forceinline__ float tfr(float x) { return __uint_as_float(f2tf(x)); }
__device__ __forceinline__ uint32_t smem_u32(const void* p) {
    uint32_t a;
    asm("{ .reg .u64 t; cvta.to.shared.u64 t, %1; cvt.u32.u64 %0, t; }" : "=r"(a) : "l"(p));
    return a;
}
__device__ __forceinline__ void cp16(uint32_t s, const void* g) {
    asm volatile("cp.async.cg.shared.global [%0], [%1], 16;" :: "r"(s), "l"(g));
}
__device__ __forceinline__ void mma8(float* d, const uint32_t* a, const uint32_t* b) {
    asm volatile(
        "mma.sync.aligned.m16n8k8.row.col.f32.tf32.tf32.f32 "
        "{%0,%1,%2,%3}, {%4,%5,%6,%7}, {%8,%9}, {%0,%1,%2,%3};"
        : "+f"(d[0]), "+f"(d[1]), "+f"(d[2]), "+f"(d[3])
        : "r"(a[0]), "r"(a[1]), "r"(a[2]), "r"(a[3]), "r"(b[0]), "r"(b[1]));
}

// ---------------------------------------------------------------------------
// Kernel 0: pre-round all weights to tf32 (Wq|Wk|Wv -> g_w, Wo -> g_wo).
// grid 512 x 256 covers exactly 512*192 + 64*512 = 131072 elements.
// ---------------------------------------------------------------------------
__global__ void __launch_bounds__(256) preround_kernel(
    const float* __restrict__ Wq, const float* __restrict__ Wk,
    const float* __restrict__ Wv, const float* __restrict__ Wo)
{
    int idx = blockIdx.x * 256 + threadIdx.x;
    if (idx < D_MODEL * 192) {
        int k = idx / 192, c = idx % 192;
        int seg = c >> 6;
        const float* src = (seg == 0) ? Wq : (seg == 1) ? Wk : Wv;
        g_w[idx] = tfr(src[k * DHEAD + (c & 63)]);
    } else {
        int i2 = idx - D_MODEL * 192;
        g_wo[i2] = tfr(Wo[i2]);
    }
}

// ---------------------------------------------------------------------------
// Kernel 1: merged QKV projection.  grid = 256, 256 thr.
// C[64 x 192] = X[64 x 512] * g_w[512 x 192]; double-buffered 32-wide chunks.
// ---------------------------------------------------------------------------
#define XSTR 36
#define WSTR 200
#define XS_SZ (64 * XSTR)
#define WS_SZ (32 * WSTR)
#define QKV_SMEM ((2 * XS_SZ + 2 * WS_SZ) * 4)

__global__ void __launch_bounds__(256, 2) qkv_tc_kernel(
    const float* __restrict__ x,
    const float* __restrict__ bq, const float* __restrict__ bk,
    const float* __restrict__ bv)
{
    extern __shared__ float smq[];
    const int tid = threadIdx.x;
    const int w = tid >> 5, lane = tid & 31, g = lane >> 2, t4 = lane & 3;
    const int wm = w & 1, wn = w >> 1;
    const int rowBase = blockIdx.x * 64;
    const uint32_t smb = smem_u32(smq);

    const int XS[2] = { 0, XS_SZ };
    const int WS[2] = { 2 * XS_SZ, 2 * XS_SZ + WS_SZ };

    const int xr = tid >> 2, xq = (tid & 3) * 8;
    const int wr = tid >> 3, wq = (tid & 7) * 24;

    // chunk 0
    {
        const float* xp = x + (size_t)(rowBase + xr) * D_MODEL + xq;
        uint32_t xa = smb + (uint32_t)(XS[0] + xr * XSTR + xq) * 4;
        cp16(xa, xp); cp16(xa + 16, xp + 4);
        const float* wp = g_w + (size_t)wr * 192 + wq;
        uint32_t wa = smb + (uint32_t)(WS[0] + wr * WSTR + wq) * 4;
        #pragma unroll
        for (int i = 0; i < 6; i++) cp16(wa + 16 * i, wp + 4 * i);
        asm volatile("cp.async.commit_group;" ::: "memory");
    }

    float acc[2][6][4] = {};

    for (int kc = 0; kc < 16; kc++) {
        __syncthreads();
        if (kc < 15) {
            const int bi = (kc + 1) & 1;
            const float* xp = x + (size_t)(rowBase + xr) * D_MODEL + (kc + 1) * 32 + xq;
            uint32_t xa = smb + (uint32_t)(XS[bi] + xr * XSTR + xq) * 4;
            cp16(xa, xp); cp16(xa + 16, xp + 4);
            const float* wp = g_w + (size_t)((kc + 1) * 32 + wr) * 192 + wq;
            uint32_t wa = smb + (uint32_t)(WS[bi] + wr * WSTR + wq) * 4;
            #pragma unroll
            for (int i = 0; i < 6; i++) cp16(wa + 16 * i, wp + 4 * i);
            asm volatile("cp.async.commit_group;" ::: "memory");
            asm volatile("cp.async.wait_group 1;" ::: "memory");
        } else {
            asm volatile("cp.async.wait_group 0;" ::: "memory");
        }
        __syncthreads();

        const float* Xb = smq + XS[kc & 1];
        const float* Wb = smq + WS[kc & 1];
        #pragma unroll
        for (int s = 0; s < 4; s++) {
            const int k0 = 8 * s;
            uint32_t af[2][4];
            #pragma unroll
            for (int i = 0; i < 2; i++) {
                const int m0 = 32 * wm + 16 * i;
                af[i][0] = f2tf(Xb[(m0 + g) * XSTR + k0 + t4]);
                af[i][1] = f2tf(Xb[(m0 + g + 8) * XSTR + k0 + t4]);
                af[i][2] = f2tf(Xb[(m0 + g) * XSTR + k0 + t4 + 4]);
                af[i][3] = f2tf(Xb[(m0 + g + 8) * XSTR + k0 + t4 + 4]);
            }
            #pragma unroll
            for (int nt = 0; nt < 6; nt++) {
                const int n0 = 48 * wn + 8 * nt;
                uint32_t bf[2];
                bf[0] = __float_as_uint(Wb[(k0 + t4) * WSTR + n0 + g]);
                bf[1] = __float_as_uint(Wb[(k0 + t4 + 4) * WSTR + n0 + g]);
                mma8(acc[0][nt], af[0], bf);
                mma8(acc[1][nt], af[1], bf);
            }
        }
    }

    // epilogue: +bias, round to tf32, store to segment
    #pragma unroll
    for (int nt = 0; nt < 6; nt++) {
        const int colg = 48 * wn + 8 * nt + 2 * t4;
        const int seg = colg >> 6, ci = colg & 63;
        const float* bias = (seg == 0) ? bq : (seg == 1) ? bk : bv;
        float* dst = (seg == 0) ? g_q : (seg == 1) ? g_k : g_v;
        const float b0 = bias[ci], b1 = bias[ci + 1];
        #pragma unroll
        for (int i = 0; i < 2; i++) {
            const int rA = rowBase + 32 * wm + 16 * i + g;
            *(float2*)&dst[(size_t)rA * DHEAD + ci] =
                make_float2(tfr(acc[i][nt][0] + b0), tfr(acc[i][nt][1] + b1));
            *(float2*)&dst[(size_t)(rA + 8) * DHEAD + ci] =
                make_float2(tfr(acc[i][nt][2] + b0), tfr(acc[i][nt][3] + b1));
        }
    }
}

// ---------------------------------------------------------------------------
// Kernel 2: tf32 mma.sync causal flash attention, in-register P.
// grid = (64, B), 128 thr. CTA = 64 q rows (j = 63 - bx, longest first).
// Warp w owns q rows 16w..16w+15 across the FULL 64-key tile; the S fragment
// is permuted to a PV A-fragment with intra-quad shuffles (no smem P).
// ---------------------------------------------------------------------------
#define KSTR 68
#define VSTR 72
#define AQ   0
#define AK0  4352
#define AK1  8704
#define AV0  13056
#define AV1  17664
#define ATTN_SMEM (22272 * 4)

__global__ void __launch_bounds__(128, 2) attn_mma_kernel()
{
    extern __shared__ float sm[];
    const int tid  = threadIdx.x;
    const int w    = tid >> 5, lane = tid & 31;
    const int g    = lane >> 2, t4 = lane & 3;
    const int b    = blockIdx.y;
    const int j    = 63 - (int)blockIdx.x;     // longest CTAs launch first
    const int qr0  = 16 * w;
    const uint32_t smb = smem_u32(sm);

    const float* kg = g_k + (size_t)b * S_LEN * DHEAD;
    const float* vg = g_v + (size_t)b * S_LEN * DHEAD;
    const float SCL2 = 0.18033688011112042f;   // (1/8)*log2(e)
    const size_t qrow = (size_t)b * S_LEN + 64 * j;

    const int ldr = tid >> 1, ldc = (tid & 1) * 32;

    // initial: Q + K0 + V0
    {
        const float* qp = g_q + (qrow + ldr) * DHEAD + ldc;
        uint32_t qa = smb + (uint32_t)(AQ + ldr * KSTR + ldc) * 4;
        #pragma unroll
        for (int i = 0; i < 8; i++) cp16(qa + 16 * i, qp + 4 * i);
        const float* kp = kg + (size_t)ldr * DHEAD + ldc;
        uint32_t ka = smb + (uint32_t)(AK0 + ldr * KSTR + ldc) * 4;
        #pragma unroll
        for (int i = 0; i < 8; i++) cp16(ka + 16 * i, kp + 4 * i);
        const float* vp = vg + (size_t)ldr * DHEAD + ldc;
        uint32_t va = smb + (uint32_t)(AV0 + ldr * VSTR + ldc) * 4;
        #pragma unroll
        for (int i = 0; i < 8; i++) cp16(va + 16 * i, vp + 4 * i);
    }
    asm volatile("cp.async.commit_group;" ::: "memory");
    asm volatile("cp.async.wait_group 0;" ::: "memory");
    __syncthreads();

    uint32_t qf[8][4];
    #pragma unroll
    for (int s = 0; s < 8; s++) {
        const int k0 = 8 * s;
        qf[s][0] = __float_as_uint(sm[AQ + (qr0 + g) * KSTR + k0 + t4]);
        qf[s][1] = __float_as_uint(sm[AQ + (qr0 + g + 8) * KSTR + k0 + t4]);
        qf[s][2] = __float_as_uint(sm[AQ + (qr0 + g) * KSTR + k0 + t4 + 4]);
        qf[s][3] = __float_as_uint(sm[AQ + (qr0 + g + 8) * KSTR + k0 + t4 + 4]);
    }

    float oacc[8][4] = {};
    float l0 = 0.f, l1 = 0.f;
    const uint32_t srcA = (lane & ~3) | (t4 >> 1);
    const uint32_t srcB = srcA | 2;

    for (int kb = 0; kb <= j; kb++) {
        const int kO = (kb & 1) ? AK1 : AK0;
        const int vO = (kb & 1) ? AV1 : AV0;

        __syncthreads();
        if (kb < j) {
            const int nK = (kb & 1) ? AK0 : AK1;
            const int nV = (kb & 1) ? AV0 : AV1;
            const float* kp = kg + ((size_t)(kb + 1) * 64 + ldr) * DHEAD + ldc;
            uint32_t ka = smb + (uint32_t)(nK + ldr * KSTR + ldc) * 4;
            #pragma unroll
            for (int i = 0; i < 8; i++) cp16(ka + 16 * i, kp + 4 * i);
            const float* vp = vg + ((size_t)(kb + 1) * 64 + ldr) * DHEAD + ldc;
            uint32_t va = smb + (uint32_t)(nV + ldr * VSTR + ldc) * 4;
            #pragma unroll
            for (int i = 0; i < 8; i++) cp16(va + 16 * i, vp + 4 * i);
            asm volatile("cp.async.commit_group;" ::: "memory");
            asm volatile("cp.async.wait_group 1;" ::: "memory");
        } else {
            asm volatile("cp.async.wait_group 0;" ::: "memory");
        }
        __syncthreads();

        // --- S = Q K^T over the full 64-key tile ---
        float sacc[8][4] = {};
        #pragma unroll
        for (int s = 0; s < 8; s++) {
            const int k0 = 8 * s;
            #pragma unroll
            for (int nt = 0; nt < 8; nt++) {
                uint32_t bf[2];
                bf[0] = __float_as_uint(sm[kO + (8 * nt + g) * KSTR + k0 + t4]);
                bf[1] = __float_as_uint(sm[kO + (8 * nt + g) * KSTR + k0 + t4 + 4]);
                mma8(sacc[nt], qf[s], bf);
            }
        }

        // --- softmax (no-rescale), tf32-round into pt ---
        const bool dg = (kb == j);
        const int ra = qr0 + g, rb = ra + 8;
        uint32_t pt[8][4];
        #pragma unroll
        for (int nt = 0; nt < 8; nt++) {
            const int cb = 8 * nt + 2 * t4;
            float p00 = (!dg || cb     <= ra) ? tfr(ex2f(sacc[nt][0] * SCL2)) : 0.f;
            float p01 = (!dg || cb + 1 <= ra) ? tfr(ex2f(sacc[nt][1] * SCL2)) : 0.f;
            float p10 = (!dg || cb     <= rb) ? tfr(ex2f(sacc[nt][2] * SCL2)) : 0.f;
            float p11 = (!dg || cb + 1 <= rb) ? tfr(ex2f(sacc[nt][3] * SCL2)) : 0.f;
            l0 += p00 + p01;
            l1 += p10 + p11;
            pt[nt][0] = __float_as_uint(p00);
            pt[nt][1] = __float_as_uint(p01);
            pt[nt][2] = __float_as_uint(p10);
            pt[nt][3] = __float_as_uint(p11);
        }

        // --- O += P V : permute C-fragment -> A-fragment via quad shuffles ---
        #pragma unroll
        for (int s2 = 0; s2 < 8; s2++) {
            uint32_t pa[4];
            {
                uint32_t x0 = __shfl_sync(0xffffffffu, pt[s2][0], srcA);
                uint32_t x1 = __shfl_sync(0xffffffffu, pt[s2][1], srcA);
                pa[0] = (t4 & 1) ? x1 : x0;
                uint32_t y0 = __shfl_sync(0xffffffffu, pt[s2][0], srcB);
                uint32_t y1 = __shfl_sync(0xffffffffu, pt[s2][1], srcB);
                pa[2] = (t4 & 1) ? y1 : y0;
                uint32_t z0 = __shfl_sync(0xffffffffu, pt[s2][2], srcA);
                uint32_t z1 = __shfl_sync(0xffffffffu, pt[s2][3], srcA);
                pa[1] = (t4 & 1) ? z1 : z0;
                uint32_t u0 = __shfl_sync(0xffffffffu, pt[s2][2], srcB);
                uint32_t u1 = __shfl_sync(0xffffffffu, pt[s2][3], srcB);
                pa[3] = (t4 & 1) ? u1 : u0;
            }
            const int k0 = 8 * s2;
            #pragma unroll
            for (int nt2 = 0; nt2 < 8; nt2++) {
                uint32_t vb[2];
                vb[0] = __float_as_uint(sm[vO + (k0 + t4) * VSTR + 8 * nt2 + g]);
                vb[1] = __float_as_uint(sm[vO + (k0 + t4 + 4) * VSTR + 8 * nt2 + g]);
                mma8(oacc[nt2], pa, vb);
            }
        }
    }

    // --- epilogue: quad-reduce l, normalize, tf32-round, store ---
    l0 += __shfl_xor_sync(0xffffffffu, l0, 1);
    l0 += __shfl_xor_sync(0xffffffffu, l0, 2);
    l1 += __shfl_xor_sync(0xffffffffu, l1, 1);
    l1 += __shfl_xor_sync(0xffffffffu, l1, 2);
    const float iA = 1.f / l0, iB = 1.f / l1;

    float* op  = g_attn + (qrow + qr0 + g) * DHEAD;
    float* op2 = op + 8 * DHEAD;
    #pragma unroll
    for (int nt2 = 0; nt2 < 8; nt2++) {
        const int cb = 8 * nt2 + 2 * t4;
        *(float2*)&op[cb]  = make_float2(tfr(oacc[nt2][0] * iA), tfr(oacc[nt2][1] * iA));
        *(float2*)&op2[cb] = make_float2(tfr(oacc[nt2][2] * iB), tfr(oacc[nt2][3] * iB));
    }
}

// ---------------------------------------------------------------------------
// Kernel 3: tf32 tensor-core output projection.  grid = (128, 4), 256 thr.
// out[128x128] = attn[128x64] * g_wo[64x128-slice] + bo.  All inputs tf32.
// ---------------------------------------------------------------------------
#define AS_OFF 0
#define BS_STR 136
#define BS_OFF (128 * 68)
#define PROJ_SMEM ((128 * 68 + 64 * BS_STR) * 4)

__global__ void __launch_bounds__(256) proj_tc_kernel(
    const float* __restrict__ bo, float* __restrict__ out)
{
    extern __shared__ float smp[];
    const int tid = threadIdx.x;
    const int w = tid >> 5, lane = tid & 31, g = lane >> 2, t4 = lane & 3;
    const int wm = w & 3, wn = w >> 2;
    const int rowBase = blockIdx.x * 128;
    const int nBase   = blockIdx.y * 128;
    const uint32_t smb = smem_u32(smp);

    {
        const int ar = tid >> 1, ac = (tid & 1) * 32;
        const float* ap = g_attn + (size_t)(rowBase + ar) * DHEAD + ac;
        uint32_t aa = smb + (uint32_t)(AS_OFF + ar * 68 + ac) * 4;
        #pragma unroll
        for (int i = 0; i < 8; i++) cp16(aa + 16 * i, ap + 4 * i);
        const int br = tid >> 2, bc = (tid & 3) * 32;
        const float* bp = g_wo + (size_t)br * D_MODEL + nBase + bc;
        uint32_t ba = smb + (uint32_t)(BS_OFF + br * BS_STR + bc) * 4;
        #pragma unroll
        for (int i = 0; i < 8; i++) cp16(ba + 16 * i, bp + 4 * i);
    }
    asm volatile("cp.async.commit_group;" ::: "memory");
    asm volatile("cp.async.wait_group 0;" ::: "memory");
    __syncthreads();

    float acc[2][8][4] = {};
    #pragma unroll
    for (int s = 0; s < 8; s++) {
        const int k0 = 8 * s;
        uint32_t af[2][4];
        #pragma unroll
        for (int i = 0; i < 2; i++) {
            const int m0 = 32 * wm + 16 * i;
            af[i][0] = __float_as_uint(smp[AS_OFF + (m0 + g) * 68 + k0 + t4]);
            af[i][1] = __float_as_uint(smp[AS_OFF + (m0 + g + 8) * 68 + k0 + t4]);
            af[i][2] = __float_as_uint(smp[AS_OFF + (m0 + g) * 68 + k0 + t4 + 4]);
            af[i][3] = __float_as_uint(smp[AS_OFF + (m0 + g + 8) * 68 + k0 + t4 + 4]);
        }
        #pragma unroll
        for (int nt = 0; nt < 8; nt++) {
            const int n0 = 64 * wn + 8 * nt;
            uint32_t bf[2];
            bf[0] = __float_as_uint(smp[BS_OFF + (k0 + t4) * BS_STR + n0 + g]);
            bf[1] = __float_as_uint(smp[BS_OFF + (k0 + t4 + 4) * BS_STR + n0 + g]);
            mma8(acc[0][nt], af[0], bf);
            mma8(acc[1][nt], af[1], bf);
        }
    }

    #pragma unroll
    for (int i = 0; i < 2; i++) {
        #pragma unroll
        for (int nt = 0; nt < 8; nt++) {
            const int col = nBase + 64 * wn + 8 * nt + 2 * t4;
            const float b0 = bo[col], b1 = bo[col + 1];
            const int rA = rowBase + 32 * wm + 16 * i + g;
            *(float2*)&out[(size_t)rA * D_MODEL + col] =
                make_float2(acc[i][nt][0] + b0, acc[i][nt][1] + b1);
            *(float2*)&out[(size_t)(rA + 8) * D_MODEL + col] =
                make_float2(acc[i][nt][2] + b0, acc[i][nt][3] + b1);
        }
    }
}

// ---------------------------------------------------------------------------
extern "C" void kernel_launch(void* const* d_in, const int* in_sizes, int n_in,
                              void* d_out, int out_size)
{
    const float* x  = (const float*)d_in[0];
    const float* Wq = (const float*)d_in[1];
    const float* bq = (const float*)d_in[2];
    const float* Wk = (const float*)d_in[3];
    const float* bk = (const float*)d_in[4];
    const float* Wv = (const float*)d_in[5];
    const float* bv = (const float*)d_in[6];
    const float* Wo = (const float*)d_in[7];
    const float* bo = (const float*)d_in[8];
    float* out = (float*)d_out;

    cudaFuncSetAttribute(qkv_tc_kernel,
                         cudaFuncAttributeMaxDynamicSharedMemorySize, QKV_SMEM);
    cudaFuncSetAttribute(attn_mma_kernel,
                         cudaFuncAttributeMaxDynamicSharedMemorySize, ATTN_SMEM);
    cudaFuncSetAttribute(proj_tc_kernel,
                         cudaFuncAttributeMaxDynamicSharedMemorySize, PROJ_SMEM);

    preround_kernel<<<512, 256>>>(Wq, Wk, Wv, Wo);
    qkv_tc_kernel<<<BSROWS / 64, 256, QKV_SMEM>>>(x, bq, bk, bv);
    attn_mma_kernel<<<dim3(64, BATCH), 128, ATTN_SMEM>>>();
    proj_tc_kernel<<<dim3(BSROWS / 128, D_MODEL / 128), 256, PROJ_SMEM>>>(bo, out);
}

// round 6
// speedup vs baseline: 1.4451x; 1.4451x over previous
#include <cuda_runtime.h>
#include <cstdint>

#define S_LEN   4096
#define BATCH   4
#define D_MODEL 512
#define DHEAD   64
#define BSROWS  (BATCH * S_LEN)
#define PAD     68

// Scratch (allocation-free rule: __device__ globals)
__device__ float g_x[BSROWS * D_MODEL];   // tf32 bits
__device__ float g_q[BSROWS * DHEAD];     // tf32 bits
__device__ float g_k[BSROWS * DHEAD];     // tf32 bits
__device__ float g_v[BSROWS * DHEAD];     // tf32 bits
__device__ float g_attn[BSROWS * DHEAD];  // tf32 bits
__device__ float g_wq[D_MODEL * DHEAD];   // tf32 bits
__device__ float g_wk[D_MODEL * DHEAD];   // tf32 bits
__device__ float g_wv[D_MODEL * DHEAD];   // tf32 bits
__device__ float g_wo[DHEAD * D_MODEL];   // tf32 bits

__device__ __forceinline__ float ex2f(float x) {
    float y; asm("ex2.approx.f32 %0, %1;" : "=f"(y) : "f"(x)); return y;
}
__device__ __forceinline__ uint32_t f2tf(float x) {
    uint32_t r; asm("cvt.rna.tf32.f32 %0, %1;" : "=r"(r) : "f"(x)); return r;
}
__device__ __forceinline__ float tfr(float x) { return __uint_as_float(f2tf(x)); }
__device__ __forceinline__ uint32_t smem_u32(const void* p) {
    uint32_t a;
    asm("{ .reg .u64 t; cvta.to.shared.u64 t, %1; cvt.u32.u64 %0, t; }" : "=r"(a) : "l"(p));
    return a;
}
__device__ __forceinline__ void cp16(uint32_t s, const void* g) {
    asm volatile("cp.async.cg.shared.global [%0], [%1], 16;" :: "r"(s), "l"(g));
}
__device__ __forceinline__ void mma8(float* d, const uint32_t* a, const uint32_t* b) {
    asm volatile(
        "mma.sync.aligned.m16n8k8.row.col.f32.tf32.tf32.f32 "
        "{%0,%1,%2,%3}, {%4,%5,%6,%7}, {%8,%9}, {%0,%1,%2,%3};"
        : "+f"(d[0]), "+f"(d[1]), "+f"(d[2]), "+f"(d[3])
        : "r"(a[0]), "r"(a[1]), "r"(a[2]), "r"(a[3]), "r"(b[0]), "r"(b[1]));
}

// ---------------------------------------------------------------------------
// Kernel 0: pre-round x and all weights to tf32 (vectorized grid-stride).
// ---------------------------------------------------------------------------
#define N4X (BSROWS * D_MODEL / 4)
#define N4W (D_MODEL * DHEAD / 4)

__global__ void __launch_bounds__(256) preround_kernel(
    const float4* __restrict__ x4,
    const float4* __restrict__ wq4, const float4* __restrict__ wk4,
    const float4* __restrict__ wv4, const float4* __restrict__ wo4)
{
    const int total = N4X + 4 * N4W;
    for (int i = blockIdx.x * blockDim.x + threadIdx.x; i < total;
         i += gridDim.x * blockDim.x) {
        float4 v; float4* dst;
        if (i < N4X) {
            v = x4[i];
            dst = reinterpret_cast<float4*>(g_x) + i;
        } else {
            int r = i - N4X;
            int seg = r / N4W, o = r % N4W;
            const float4* s = (seg == 0) ? wq4 : (seg == 1) ? wk4 : (seg == 2) ? wv4 : wo4;
            float* d = (seg == 0) ? g_wq : (seg == 1) ? g_wk : (seg == 2) ? g_wv : g_wo;
            v = s[o];
            dst = reinterpret_cast<float4*>(d) + o;
        }
        v.x = tfr(v.x); v.y = tfr(v.y); v.z = tfr(v.z); v.w = tfr(v.w);
        *dst = v;
    }
}

// ---------------------------------------------------------------------------
// Kernel 1: tf32 tensor-core QKV projection (R4 structure, pre-rounded in).
// grid = (128, 3), 256 thr. C[128x64] = g_x[128x512] * g_w*[512x64].
// ---------------------------------------------------------------------------
#define XS_SZ   (128 * 36)
#define WS_SZ   (32 * 68)
#define QKV_SMEM ((2 * XS_SZ + 2 * WS_SZ) * 4)

__global__ void __launch_bounds__(256) qkv_tc_kernel(
    const float* __restrict__ bq, const float* __restrict__ bk,
    const float* __restrict__ bv)
{
    extern __shared__ float smq[];
    const int mode = blockIdx.y;
    const float* W    = (mode == 0) ? g_wq : (mode == 1) ? g_wk : g_wv;
    const float* bias = (mode == 0) ? bq : (mode == 1) ? bk : bv;
    float* dst        = (mode == 0) ? g_q : (mode == 1) ? g_k : g_v;

    const int tid = threadIdx.x;
    const int w = tid >> 5, lane = tid & 31, g = lane >> 2, t4 = lane & 3;
    const int wm = w & 3, wn = w >> 2;
    const int rowBase = blockIdx.x * 128;
    const uint32_t smb = smem_u32(smq);

    const int XS[2] = { 0, XS_SZ };
    const int WS[2] = { 2 * XS_SZ, 2 * XS_SZ + WS_SZ };

    const int xr = tid >> 1, xc = (tid & 1) * 16;
    const int wr = tid >> 3, wc = (tid & 7) * 8;

    // chunk 0
    {
        const float* xp = g_x + (size_t)(rowBase + xr) * D_MODEL + xc;
        uint32_t xa = smb + (uint32_t)(XS[0] + xr * 36 + xc) * 4;
        cp16(xa, xp); cp16(xa + 16, xp + 4); cp16(xa + 32, xp + 8); cp16(xa + 48, xp + 12);
        const float* wp = W + (size_t)wr * DHEAD + wc;
        uint32_t wa = smb + (uint32_t)(WS[0] + wr * 68 + wc) * 4;
        cp16(wa, wp); cp16(wa + 16, wp + 4);
        asm volatile("cp.async.commit_group;" ::: "memory");
    }

    float acc[2][4][4] = {};

    for (int kc = 0; kc < 16; kc++) {
        __syncthreads();
        if (kc < 15) {
            const int bi = (kc + 1) & 1;
            const float* xp = g_x + (size_t)(rowBase + xr) * D_MODEL + (kc + 1) * 32 + xc;
            uint32_t xa = smb + (uint32_t)(XS[bi] + xr * 36 + xc) * 4;
            cp16(xa, xp); cp16(xa + 16, xp + 4); cp16(xa + 32, xp + 8); cp16(xa + 48, xp + 12);
            const float* wp = W + (size_t)((kc + 1) * 32 + wr) * DHEAD + wc;
            uint32_t wa = smb + (uint32_t)(WS[bi] + wr * 68 + wc) * 4;
            cp16(wa, wp); cp16(wa + 16, wp + 4);
            asm volatile("cp.async.commit_group;" ::: "memory");
            asm volatile("cp.async.wait_group 1;" ::: "memory");
        } else {
            asm volatile("cp.async.wait_group 0;" ::: "memory");
        }
        __syncthreads();

        const float* Xb = smq + XS[kc & 1];
        const float* Wb = smq + WS[kc & 1];
        #pragma unroll
        for (int s = 0; s < 4; s++) {
            const int k0 = 8 * s;
            uint32_t af[2][4];
            #pragma unroll
            for (int i = 0; i < 2; i++) {
                const int m0 = 32 * wm + 16 * i;
                af[i][0] = __float_as_uint(Xb[(m0 + g) * 36 + k0 + t4]);
                af[i][1] = __float_as_uint(Xb[(m0 + g + 8) * 36 + k0 + t4]);
                af[i][2] = __float_as_uint(Xb[(m0 + g) * 36 + k0 + t4 + 4]);
                af[i][3] = __float_as_uint(Xb[(m0 + g + 8) * 36 + k0 + t4 + 4]);
            }
            #pragma unroll
            for (int nt = 0; nt < 4; nt++) {
                const int n0 = 32 * wn + 8 * nt;
                uint32_t bf[2];
                bf[0] = __float_as_uint(Wb[(k0 + t4) * 68 + n0 + g]);
                bf[1] = __float_as_uint(Wb[(k0 + t4 + 4) * 68 + n0 + g]);
                mma8(acc[0][nt], af[0], bf);
                mma8(acc[1][nt], af[1], bf);
            }
        }
    }

    #pragma unroll
    for (int i = 0; i < 2; i++) {
        #pragma unroll
        for (int nt = 0; nt < 4; nt++) {
            const int col = 32 * wn + 8 * nt + 2 * t4;
            const float b0 = bias[col], b1 = bias[col + 1];
            const int rA = rowBase + 32 * wm + 16 * i + g;
            *(float2*)&dst[(size_t)rA * DHEAD + col] =
                make_float2(tfr(acc[i][nt][0] + b0), tfr(acc[i][nt][1] + b1));
            *(float2*)&dst[(size_t)(rA + 8) * DHEAD + col] =
                make_float2(tfr(acc[i][nt][2] + b0), tfr(acc[i][nt][3] + b1));
        }
    }
}

// smem float offsets (attention)
#define QO  0
#define PO  4352
#define K0O 8704
#define V0O 13056
#define K1O 17408
#define V1O 21760
#define LO  26112
#define SM_FLOATS 26368
#define ATTN_SMEM (SM_FLOATS * 4)

// ---------------------------------------------------------------------------
// Kernel 2: tf32 mma.sync causal flash attention (R4 algorithm, 512 thr).
// grid = (32 pairs, B). CTA processes q-blocks j and 63-j (64 rows each)
// -> exactly 65 key-tiles per CTA (perfect causal balance).
// 16 warps: wm = w&3 -> q rows 16*wm.., wn = w>>2 -> key/dv cols 16*wn..
// ---------------------------------------------------------------------------
__global__ void __launch_bounds__(512, 1) attn_mma_kernel()
{
    extern __shared__ float sm[];
    const int tid  = threadIdx.x;
    const int w    = tid >> 5, lane = tid & 31;
    const int g    = lane >> 2, t4 = lane & 3;
    const int b    = blockIdx.y;
    const int wm   = w & 3, wn = w >> 2;
    const int qr0  = 16 * wm;
    const int nc0  = 16 * wn;
    const uint32_t smb = smem_u32(sm);

    const float* kg = g_k + (size_t)b * S_LEN * DHEAD;
    const float* vg = g_v + (size_t)b * S_LEN * DHEAD;
    const float SCL2 = 0.18033688011112042f;   // (1/8)*log2(e)

    const int ldr = tid >> 3, ldc = (tid & 7) * 8;

    int jlist[2] = { (int)blockIdx.x, 63 - (int)blockIdx.x };

    #pragma unroll 1
    for (int pb = 0; pb < 2; pb++) {
        const int j = jlist[pb];
        const size_t qrow = (size_t)b * S_LEN + 64 * j;

        {
            const float* qp = g_q + (qrow + ldr) * DHEAD + ldc;
            uint32_t qa = smb + (uint32_t)(QO + ldr * PAD + ldc) * 4;
            cp16(qa, qp); cp16(qa + 16, qp + 4);
            const float* kp = kg + (size_t)ldr * DHEAD + ldc;
            uint32_t ka = smb + (uint32_t)(K0O + ldr * PAD + ldc) * 4;
            cp16(ka, kp); cp16(ka + 16, kp + 4);
            const float* vp = vg + (size_t)ldr * DHEAD + ldc;
            uint32_t va = smb + (uint32_t)(V0O + ldr * PAD + ldc) * 4;
            cp16(va, vp); cp16(va + 16, vp + 4);
        }
        asm volatile("cp.async.commit_group;" ::: "memory");
        asm volatile("cp.async.wait_group 0;" ::: "memory");
        __syncthreads();

        uint32_t qf[8][4];
        #pragma unroll
        for (int s = 0; s < 8; s++) {
            const int k0 = 8 * s;
            qf[s][0] = __float_as_uint(sm[QO + (qr0 + g) * PAD + k0 + t4]);
            qf[s][1] = __float_as_uint(sm[QO + (qr0 + g + 8) * PAD + k0 + t4]);
            qf[s][2] = __float_as_uint(sm[QO + (qr0 + g) * PAD + k0 + t4 + 4]);
            qf[s][3] = __float_as_uint(sm[QO + (qr0 + g + 8) * PAD + k0 + t4 + 4]);
        }

        float oacc[2][4] = {};
        float l0 = 0.f, l1 = 0.f;

        for (int kb = 0; kb <= j; kb++) {
            const int kOff = (kb & 1) ? K1O : K0O;
            const int vOff = (kb & 1) ? V1O : V0O;

            __syncthreads();

            if (kb < j) {
                const int nK = (kb & 1) ? K0O : K1O;
                const int nV = (kb & 1) ? V0O : V1O;
                const float* kp = kg + ((size_t)(kb + 1) * 64 + ldr) * DHEAD + ldc;
                uint32_t ka = smb + (uint32_t)(nK + ldr * PAD + ldc) * 4;
                cp16(ka, kp); cp16(ka + 16, kp + 4);
                const float* vp = vg + ((size_t)(kb + 1) * 64 + ldr) * DHEAD + ldc;
                uint32_t va = smb + (uint32_t)(nV + ldr * PAD + ldc) * 4;
                cp16(va, vp); cp16(va + 16, vp + 4);
                asm volatile("cp.async.commit_group;" ::: "memory");
                asm volatile("cp.async.wait_group 1;" ::: "memory");
            } else {
                asm volatile("cp.async.wait_group 0;" ::: "memory");
            }
            __syncthreads();

            // --- S = Q K^T : 2 n-tiles x 8 k-steps ---
            float sacc[2][4] = {};
            #pragma unroll
            for (int s = 0; s < 8; s++) {
                const int k0 = 8 * s;
                #pragma unroll
                for (int nt = 0; nt < 2; nt++) {
                    const int n0 = nc0 + 8 * nt;
                    uint32_t bf[2];
                    bf[0] = __float_as_uint(sm[kOff + (n0 + g) * PAD + k0 + t4]);
                    bf[1] = __float_as_uint(sm[kOff + (n0 + g) * PAD + k0 + t4 + 4]);
                    mma8(sacc[nt], qf[s], bf);
                }
            }

            // --- softmax (no max subtraction), write P (tf32 bits) ---
            const bool dg = (kb == j);
            const int ra = qr0 + g, rb = ra + 8;
            #pragma unroll
            for (int nt = 0; nt < 2; nt++) {
                const int cb = nc0 + 8 * nt + 2 * t4;
                float p00 = (!dg || cb     <= ra) ? ex2f(sacc[nt][0] * SCL2) : 0.f;
                float p01 = (!dg || cb + 1 <= ra) ? ex2f(sacc[nt][1] * SCL2) : 0.f;
                float p10 = (!dg || cb     <= rb) ? ex2f(sacc[nt][2] * SCL2) : 0.f;
                float p11 = (!dg || cb + 1 <= rb) ? ex2f(sacc[nt][3] * SCL2) : 0.f;
                l0 += p00 + p01;
                l1 += p10 + p11;
                sm[PO + ra * PAD + cb]     = __uint_as_float(f2tf(p00));
                sm[PO + ra * PAD + cb + 1] = __uint_as_float(f2tf(p01));
                sm[PO + rb * PAD + cb]     = __uint_as_float(f2tf(p10));
                sm[PO + rb * PAD + cb + 1] = __uint_as_float(f2tf(p11));
            }
            __syncthreads();

            // --- O += P V : 8 k-steps x 2 n-tiles ---
            #pragma unroll
            for (int s = 0; s < 8; s++) {
                const int k0 = 8 * s;
                uint32_t pa[4];
                pa[0] = __float_as_uint(sm[PO + (qr0 + g) * PAD + k0 + t4]);
                pa[1] = __float_as_uint(sm[PO + (qr0 + g + 8) * PAD + k0 + t4]);
                pa[2] = __float_as_uint(sm[PO + (qr0 + g) * PAD + k0 + t4 + 4]);
                pa[3] = __float_as_uint(sm[PO + (qr0 + g + 8) * PAD + k0 + t4 + 4]);
                #pragma unroll
                for (int nt = 0; nt < 2; nt++) {
                    const int n0 = nc0 + 8 * nt;
                    uint32_t vb[2];
                    vb[0] = __float_as_uint(sm[vOff + (k0 + t4) * PAD + n0 + g]);
                    vb[1] = __float_as_uint(sm[vOff + (k0 + t4 + 4) * PAD + n0 + g]);
                    mma8(oacc[nt], pa, vb);
                }
            }
        }

        // --- epilogue: quad-reduce l, combine across 4 n-warps, store ---
        l0 += __shfl_xor_sync(0xffffffffu, l0, 1);
        l0 += __shfl_xor_sync(0xffffffffu, l0, 2);
        l1 += __shfl_xor_sync(0xffffffffu, l1, 1);
        l1 += __shfl_xor_sync(0xffffffffu, l1, 2);
        if (t4 == 0) {
            sm[LO + w * 16 + g]     = l0;
            sm[LO + w * 16 + g + 8] = l1;
        }
        __syncthreads();
        float sA = 0.f, sB = 0.f;
        #pragma unroll
        for (int k = 0; k < 4; k++) {
            sA += sm[LO + (wm + 4 * k) * 16 + g];
            sB += sm[LO + (wm + 4 * k) * 16 + g + 8];
        }
        const float iA = 1.f / sA, iB = 1.f / sB;

        float* op  = g_attn + (qrow + qr0 + g) * DHEAD;
        float* op2 = op + 8 * DHEAD;
        #pragma unroll
        for (int nt = 0; nt < 2; nt++) {
            const int cb = nc0 + 8 * nt + 2 * t4;
            *(float2*)&op[cb]  = make_float2(tfr(oacc[nt][0] * iA), tfr(oacc[nt][1] * iA));
            *(float2*)&op2[cb] = make_float2(tfr(oacc[nt][2] * iB), tfr(oacc[nt][3] * iB));
        }
        __syncthreads();
    }
}

// ---------------------------------------------------------------------------
// Kernel 3: tf32 tensor-core output projection (R4 structure, g_wo bits).
// grid = (128, 4), 256 thr. out[128x128] = attn[128x64] * Wo[64x128] + bo.
// ---------------------------------------------------------------------------
#define AS_OFF 0
#define BS_OFF (128 * 68)
#define PROJ_SMEM ((128 * 68 + 64 * 132) * 4)

__global__ void __launch_bounds__(256) proj_tc_kernel(
    const float* __restrict__ bo, float* __restrict__ out)
{
    extern __shared__ float smp[];
    const int tid = threadIdx.x;
    const int w = tid >> 5, lane = tid & 31, g = lane >> 2, t4 = lane & 3;
    const int wm = w & 3, wn = w >> 2;
    const int rowBase = blockIdx.x * 128;
    const int nBase   = blockIdx.y * 128;
    const uint32_t smb = smem_u32(smp);

    {
        const int ar = tid >> 1, ac = (tid & 1) * 32;
        const float* ap = g_attn + (size_t)(rowBase + ar) * DHEAD + ac;
        uint32_t aa = smb + (uint32_t)(AS_OFF + ar * 68 + ac) * 4;
        #pragma unroll
        for (int i = 0; i < 8; i++) cp16(aa + 16 * i, ap + 4 * i);
        const int br = tid >> 2, bc = (tid & 3) * 32;
        const float* bp = g_wo + (size_t)br * D_MODEL + nBase + bc;
        uint32_t ba = smb + (uint32_t)(BS_OFF + br * 132 + bc) * 4;
        #pragma unroll
        for (int i = 0; i < 8; i++) cp16(ba + 16 * i, bp + 4 * i);
    }
    asm volatile("cp.async.commit_group;" ::: "memory");
    asm volatile("cp.async.wait_group 0;" ::: "memory");
    __syncthreads();

    float acc[2][8][4] = {};
    #pragma unroll
    for (int s = 0; s < 8; s++) {
        const int k0 = 8 * s;
        uint32_t af[2][4];
        #pragma unroll
        for (int i = 0; i < 2; i++) {
            const int m0 = 32 * wm + 16 * i;
            af[i][0] = __float_as_uint(smp[AS_OFF + (m0 + g) * 68 + k0 + t4]);
            af[i][1] = __float_as_uint(smp[AS_OFF + (m0 + g + 8) * 68 + k0 + t4]);
            af[i][2] = __float_as_uint(smp[AS_OFF + (m0 + g) * 68 + k0 + t4 + 4]);
            af[i][3] = __float_as_uint(smp[AS_OFF + (m0 + g + 8) * 68 + k0 + t4 + 4]);
        }
        #pragma unroll
        for (int nt = 0; nt < 8; nt++) {
            const int n0 = 64 * wn + 8 * nt;
            uint32_t bf[2];
            bf[0] = __float_as_uint(smp[BS_OFF + (k0 + t4) * 132 + n0 + g]);
            bf[1] = __float_as_uint(smp[BS_OFF + (k0 + t4 + 4) * 132 + n0 + g]);
            mma8(acc[0][nt], af[0], bf);
            mma8(acc[1][nt], af[1], bf);
        }
    }

    #pragma unroll
    for (int i = 0; i < 2; i++) {
        #pragma unroll
        for (int nt = 0; nt < 8; nt++) {
            const int col = nBase + 64 * wn + 8 * nt + 2 * t4;
            const float b0 = bo[col], b1 = bo[col + 1];
            const int rA = rowBase + 32 * wm + 16 * i + g;
            *(float2*)&out[(size_t)rA * D_MODEL + col] =
                make_float2(acc[i][nt][0] + b0, acc[i][nt][1] + b1);
            *(float2*)&out[(size_t)(rA + 8) * D_MODEL + col] =
                make_float2(acc[i][nt][2] + b0, acc[i][nt][3] + b1);
        }
    }
}

// ---------------------------------------------------------------------------
extern "C" void kernel_launch(void* const* d_in, const int* in_sizes, int n_in,
                              void* d_out, int out_size)
{
    const float* x  = (const float*)d_in[0];
    const float* Wq = (const float*)d_in[1];
    const float* bq = (const float*)d_in[2];
    const float* Wk = (const float*)d_in[3];
    const float* bk = (const float*)d_in[4];
    const float* Wv = (const float*)d_in[5];
    const float* bv = (const float*)d_in[6];
    const float* Wo = (const float*)d_in[7];
    const float* bo = (const float*)d_in[8];
    float* out = (float*)d_out;

    cudaFuncSetAttribute(qkv_tc_kernel,
                         cudaFuncAttributeMaxDynamicSharedMemorySize, QKV_SMEM);
    cudaFuncSetAttribute(attn_mma_kernel,
                         cudaFuncAttributeMaxDynamicSharedMemorySize, ATTN_SMEM);
    cudaFuncSetAttribute(proj_tc_kernel,
                         cudaFuncAttributeMaxDynamicSharedMemorySize, PROJ_SMEM);

    preround_kernel<<<2048, 256>>>((const float4*)x, (const float4*)Wq,
                                   (const float4*)Wk, (const float4*)Wv,
                                   (const float4*)Wo);
    qkv_tc_kernel<<<dim3(BSROWS / 128, 3), 256, QKV_SMEM>>>(bq, bk, bv);
    attn_mma_kernel<<<dim3(32, BATCH), 512, ATTN_SMEM>>>();
    proj_tc_kernel<<<dim3(BSROWS / 128, D_MODEL / 128), 256, PROJ_SMEM>>>(bo, out);
}

// round 7
// speedup vs baseline: 1.4630x; 1.0124x over previous
#include <cuda_runtime.h>
#include <cstdint>

#define S_LEN   4096
#define BATCH   4
#define D_MODEL 512
#define DHEAD   64
#define BSROWS  (BATCH * S_LEN)
#define PAD     68

// Scratch (allocation-free rule: __device__ globals)
__device__ float g_x[BSROWS * D_MODEL];   // tf32 bits
__device__ float g_q[BSROWS * DHEAD];     // tf32 bits
__device__ float g_k[BSROWS * DHEAD];     // tf32 bits
__device__ float g_v[BSROWS * DHEAD];     // tf32 bits
__device__ float g_attn[BSROWS * DHEAD];  // tf32 bits
__device__ float g_wq[D_MODEL * DHEAD];   // tf32 bits
__device__ float g_wk[D_MODEL * DHEAD];   // tf32 bits
__device__ float g_wv[D_MODEL * DHEAD];   // tf32 bits
__device__ float g_wo[DHEAD * D_MODEL];   // tf32 bits

__device__ __forceinline__ float ex2f(float x) {
    float y; asm("ex2.approx.f32 %0, %1;" : "=f"(y) : "f"(x)); return y;
}
__device__ __forceinline__ uint32_t f2tf(float x) {
    uint32_t r; asm("cvt.rna.tf32.f32 %0, %1;" : "=r"(r) : "f"(x)); return r;
}
__device__ __forceinline__ float tfr(float x) { return __uint_as_float(f2tf(x)); }
__device__ __forceinline__ uint32_t smem_u32(const void* p) {
    uint32_t a;
    asm("{ .reg .u64 t; cvta.to.shared.u64 t, %1; cvt.u32.u64 %0, t; }" : "=r"(a) : "l"(p));
    return a;
}
__device__ __forceinline__ void cp16(uint32_t s, const void* g) {
    asm volatile("cp.async.cg.shared.global [%0], [%1], 16;" :: "r"(s), "l"(g));
}
__device__ __forceinline__ void mma8(float* d, const uint32_t* a, const uint32_t* b) {
    asm volatile(
        "mma.sync.aligned.m16n8k8.row.col.f32.tf32.tf32.f32 "
        "{%0,%1,%2,%3}, {%4,%5,%6,%7}, {%8,%9}, {%0,%1,%2,%3};"
        : "+f"(d[0]), "+f"(d[1]), "+f"(d[2]), "+f"(d[3])
        : "r"(a[0]), "r"(a[1]), "r"(a[2]), "r"(a[3]), "r"(b[0]), "r"(b[1]));
}

// ---------------------------------------------------------------------------
// Kernel 0: pre-round x and all weights to tf32 (vectorized grid-stride).
// ---------------------------------------------------------------------------
#define N4X (BSROWS * D_MODEL / 4)
#define N4W (D_MODEL * DHEAD / 4)

__global__ void __launch_bounds__(256) preround_kernel(
    const float4* __restrict__ x4,
    const float4* __restrict__ wq4, const float4* __restrict__ wk4,
    const float4* __restrict__ wv4, const float4* __restrict__ wo4)
{
    const int total = N4X + 4 * N4W;
    for (int i = blockIdx.x * blockDim.x + threadIdx.x; i < total;
         i += gridDim.x * blockDim.x) {
        float4 v; float4* dst;
        if (i < N4X) {
            v = x4[i];
            dst = reinterpret_cast<float4*>(g_x) + i;
        } else {
            int r = i - N4X;
            int seg = r / N4W, o = r % N4W;
            const float4* s = (seg == 0) ? wq4 : (seg == 1) ? wk4 : (seg == 2) ? wv4 : wo4;
            float* d = (seg == 0) ? g_wq : (seg == 1) ? g_wk : (seg == 2) ? g_wv : g_wo;
            v = s[o];
            dst = reinterpret_cast<float4*>(d) + o;
        }
        v.x = tfr(v.x); v.y = tfr(v.y); v.z = tfr(v.z); v.w = tfr(v.w);
        *dst = v;
    }
}

// ---------------------------------------------------------------------------
// Kernel 1: tf32 tensor-core QKV projection (unchanged from R6).
// ---------------------------------------------------------------------------
#define XS_SZ   (128 * 36)
#define WS_SZ   (32 * 68)
#define QKV_SMEM ((2 * XS_SZ + 2 * WS_SZ) * 4)

__global__ void __launch_bounds__(256) qkv_tc_kernel(
    const float* __restrict__ bq, const float* __restrict__ bk,
    const float* __restrict__ bv)
{
    extern __shared__ float smq[];
    const int mode = blockIdx.y;
    const float* W    = (mode == 0) ? g_wq : (mode == 1) ? g_wk : g_wv;
    const float* bias = (mode == 0) ? bq : (mode == 1) ? bk : bv;
    float* dst        = (mode == 0) ? g_q : (mode == 1) ? g_k : g_v;

    const int tid = threadIdx.x;
    const int w = tid >> 5, lane = tid & 31, g = lane >> 2, t4 = lane & 3;
    const int wm = w & 3, wn = w >> 2;
    const int rowBase = blockIdx.x * 128;
    const uint32_t smb = smem_u32(smq);

    const int XS[2] = { 0, XS_SZ };
    const int WS[2] = { 2 * XS_SZ, 2 * XS_SZ + WS_SZ };

    const int xr = tid >> 1, xc = (tid & 1) * 16;
    const int wr = tid >> 3, wc = (tid & 7) * 8;

    {
        const float* xp = g_x + (size_t)(rowBase + xr) * D_MODEL + xc;
        uint32_t xa = smb + (uint32_t)(XS[0] + xr * 36 + xc) * 4;
        cp16(xa, xp); cp16(xa + 16, xp + 4); cp16(xa + 32, xp + 8); cp16(xa + 48, xp + 12);
        const float* wp = W + (size_t)wr * DHEAD + wc;
        uint32_t wa = smb + (uint32_t)(WS[0] + wr * 68 + wc) * 4;
        cp16(wa, wp); cp16(wa + 16, wp + 4);
        asm volatile("cp.async.commit_group;" ::: "memory");
    }

    float acc[2][4][4] = {};

    for (int kc = 0; kc < 16; kc++) {
        __syncthreads();
        if (kc < 15) {
            const int bi = (kc + 1) & 1;
            const float* xp = g_x + (size_t)(rowBase + xr) * D_MODEL + (kc + 1) * 32 + xc;
            uint32_t xa = smb + (uint32_t)(XS[bi] + xr * 36 + xc) * 4;
            cp16(xa, xp); cp16(xa + 16, xp + 4); cp16(xa + 32, xp + 8); cp16(xa + 48, xp + 12);
            const float* wp = W + (size_t)((kc + 1) * 32 + wr) * DHEAD + wc;
            uint32_t wa = smb + (uint32_t)(WS[bi] + wr * 68 + wc) * 4;
            cp16(wa, wp); cp16(wa + 16, wp + 4);
            asm volatile("cp.async.commit_group;" ::: "memory");
            asm volatile("cp.async.wait_group 1;" ::: "memory");
        } else {
            asm volatile("cp.async.wait_group 0;" ::: "memory");
        }
        __syncthreads();

        const float* Xb = smq + XS[kc & 1];
        const float* Wb = smq + WS[kc & 1];
        #pragma unroll
        for (int s = 0; s < 4; s++) {
            const int k0 = 8 * s;
            uint32_t af[2][4];
            #pragma unroll
            for (int i = 0; i < 2; i++) {
                const int m0 = 32 * wm + 16 * i;
                af[i][0] = __float_as_uint(Xb[(m0 + g) * 36 + k0 + t4]);
                af[i][1] = __float_as_uint(Xb[(m0 + g + 8) * 36 + k0 + t4]);
                af[i][2] = __float_as_uint(Xb[(m0 + g) * 36 + k0 + t4 + 4]);
                af[i][3] = __float_as_uint(Xb[(m0 + g + 8) * 36 + k0 + t4 + 4]);
            }
            #pragma unroll
            for (int nt = 0; nt < 4; nt++) {
                const int n0 = 32 * wn + 8 * nt;
                uint32_t bf[2];
                bf[0] = __float_as_uint(Wb[(k0 + t4) * 68 + n0 + g]);
                bf[1] = __float_as_uint(Wb[(k0 + t4 + 4) * 68 + n0 + g]);
                mma8(acc[0][nt], af[0], bf);
                mma8(acc[1][nt], af[1], bf);
            }
        }
    }

    #pragma unroll
    for (int i = 0; i < 2; i++) {
        #pragma unroll
        for (int nt = 0; nt < 4; nt++) {
            const int col = 32 * wn + 8 * nt + 2 * t4;
            const float b0 = bias[col], b1 = bias[col + 1];
            const int rA = rowBase + 32 * wm + 16 * i + g;
            *(float2*)&dst[(size_t)rA * DHEAD + col] =
                make_float2(tfr(acc[i][nt][0] + b0), tfr(acc[i][nt][1] + b1));
            *(float2*)&dst[(size_t)(rA + 8) * DHEAD + col] =
                make_float2(tfr(acc[i][nt][2] + b0), tfr(acc[i][nt][3] + b1));
        }
    }
}

// smem float offsets (attention)
#define QO  0
#define RED 4352               /* 16 warps x (16 x 68) partial-O, aliases K/V bufs */
#define K0O 8704
#define V0O 13056
#define K1O 17408
#define V1O 21760
#define LO  26112
#define SM_FLOATS 26368
#define ATTN_SMEM (SM_FLOATS * 4)

// ---------------------------------------------------------------------------
// Kernel 2: tf32 causal flash attention, split-k PV with in-register P.
// grid = (32 pairs, B), 512 thr. CTA processes q-blocks j and 63-j (64 rows
// each) -> exactly 65 key-tiles per CTA (perfect causal balance).
// Warp (wm = w&3, wk = w>>2): q rows 16*wm, keys 16*wk. After S + softmax,
// the S C-fragment is permuted in-register (quad shuffles) to the PV
// A-fragment; each warp accumulates partial O(16q x 64dv) over its 16 keys;
// partials summed across wk once per q-block through smem.
// ---------------------------------------------------------------------------
__global__ void __launch_bounds__(512, 1) attn_mma_kernel()
{
    extern __shared__ float sm[];
    const int tid  = threadIdx.x;
    const int w    = tid >> 5, lane = tid & 31;
    const int g    = lane >> 2, t4 = lane & 3;
    const int b    = blockIdx.y;
    const int wm   = w & 3, wk = w >> 2;
    const int qr0  = 16 * wm;
    const int nc0  = 16 * wk;
    const uint32_t smb = smem_u32(sm);

    const float* kg = g_k + (size_t)b * S_LEN * DHEAD;
    const float* vg = g_v + (size_t)b * S_LEN * DHEAD;
    const float SCL2 = 0.18033688011112042f;   // (1/8)*log2(e)

    const int ldr = tid >> 3, ldc = (tid & 7) * 8;
    const uint32_t srcA = (lane & ~3) | (t4 >> 1);
    const uint32_t srcB = srcA | 2;

    int jlist[2] = { (int)blockIdx.x, 63 - (int)blockIdx.x };

    #pragma unroll 1
    for (int pb = 0; pb < 2; pb++) {
        const int j = jlist[pb];
        const size_t qrow = (size_t)b * S_LEN + 64 * j;

        {
            const float* qp = g_q + (qrow + ldr) * DHEAD + ldc;
            uint32_t qa = smb + (uint32_t)(QO + ldr * PAD + ldc) * 4;
            cp16(qa, qp); cp16(qa + 16, qp + 4);
            const float* kp = kg + (size_t)ldr * DHEAD + ldc;
            uint32_t ka = smb + (uint32_t)(K0O + ldr * PAD + ldc) * 4;
            cp16(ka, kp); cp16(ka + 16, kp + 4);
            const float* vp = vg + (size_t)ldr * DHEAD + ldc;
            uint32_t va = smb + (uint32_t)(V0O + ldr * PAD + ldc) * 4;
            cp16(va, vp); cp16(va + 16, vp + 4);
        }
        asm volatile("cp.async.commit_group;" ::: "memory");
        asm volatile("cp.async.wait_group 0;" ::: "memory");
        __syncthreads();

        uint32_t qf[8][4];
        #pragma unroll
        for (int s = 0; s < 8; s++) {
            const int k0 = 8 * s;
            qf[s][0] = __float_as_uint(sm[QO + (qr0 + g) * PAD + k0 + t4]);
            qf[s][1] = __float_as_uint(sm[QO + (qr0 + g + 8) * PAD + k0 + t4]);
            qf[s][2] = __float_as_uint(sm[QO + (qr0 + g) * PAD + k0 + t4 + 4]);
            qf[s][3] = __float_as_uint(sm[QO + (qr0 + g + 8) * PAD + k0 + t4 + 4]);
        }

        float oacc[8][4] = {};     // partial O: q rows qr0.., dv 8*nt..
        float l0 = 0.f, l1 = 0.f;

        for (int kb = 0; kb <= j; kb++) {
            const int kOff = (kb & 1) ? K1O : K0O;
            const int vOff = (kb & 1) ? V1O : V0O;

            __syncthreads();   // readers of the other buffer are done

            if (kb < j) {
                const int nK = (kb & 1) ? K0O : K1O;
                const int nV = (kb & 1) ? V0O : V1O;
                const float* kp = kg + ((size_t)(kb + 1) * 64 + ldr) * DHEAD + ldc;
                uint32_t ka = smb + (uint32_t)(nK + ldr * PAD + ldc) * 4;
                cp16(ka, kp); cp16(ka + 16, kp + 4);
                const float* vp = vg + ((size_t)(kb + 1) * 64 + ldr) * DHEAD + ldc;
                uint32_t va = smb + (uint32_t)(nV + ldr * PAD + ldc) * 4;
                cp16(va, vp); cp16(va + 16, vp + 4);
                asm volatile("cp.async.commit_group;" ::: "memory");
                asm volatile("cp.async.wait_group 1;" ::: "memory");
            } else {
                asm volatile("cp.async.wait_group 0;" ::: "memory");
            }
            __syncthreads();   // tile kb visible

            // --- S = Q K^T : warp's 16x16 tile (2 n-chunks x 8 k-steps) ---
            float sacc[2][4] = {};
            #pragma unroll
            for (int s = 0; s < 8; s++) {
                const int k0 = 8 * s;
                #pragma unroll
                for (int c = 0; c < 2; c++) {
                    const int n0 = nc0 + 8 * c;
                    uint32_t bf[2];
                    bf[0] = __float_as_uint(sm[kOff + (n0 + g) * PAD + k0 + t4]);
                    bf[1] = __float_as_uint(sm[kOff + (n0 + g) * PAD + k0 + t4 + 4]);
                    mma8(sacc[c], qf[s], bf);
                }
            }

            // --- softmax (no-rescale), P kept in registers (tf32 bits) ---
            const bool dg = (kb == j);
            const int ra = qr0 + g, rb = ra + 8;
            uint32_t pt[2][4];
            #pragma unroll
            for (int c = 0; c < 2; c++) {
                const int cb = nc0 + 8 * c + 2 * t4;
                float p00 = (!dg || cb     <= ra) ? tfr(ex2f(sacc[c][0] * SCL2)) : 0.f;
                float p01 = (!dg || cb + 1 <= ra) ? tfr(ex2f(sacc[c][1] * SCL2)) : 0.f;
                float p10 = (!dg || cb     <= rb) ? tfr(ex2f(sacc[c][2] * SCL2)) : 0.f;
                float p11 = (!dg || cb + 1 <= rb) ? tfr(ex2f(sacc[c][3] * SCL2)) : 0.f;
                l0 += p00 + p01;
                l1 += p10 + p11;
                pt[c][0] = __float_as_uint(p00);
                pt[c][1] = __float_as_uint(p01);
                pt[c][2] = __float_as_uint(p10);
                pt[c][3] = __float_as_uint(p11);
            }

            // --- O_partial += P_chunk V : permute C->A frags, then MMA ---
            #pragma unroll
            for (int c = 0; c < 2; c++) {
                uint32_t pa[4];
                {
                    uint32_t x0 = __shfl_sync(0xffffffffu, pt[c][0], srcA);
                    uint32_t x1 = __shfl_sync(0xffffffffu, pt[c][1], srcA);
                    pa[0] = (t4 & 1) ? x1 : x0;
                    uint32_t z0 = __shfl_sync(0xffffffffu, pt[c][2], srcA);
                    uint32_t z1 = __shfl_sync(0xffffffffu, pt[c][3], srcA);
                    pa[1] = (t4 & 1) ? z1 : z0;
                    uint32_t y0 = __shfl_sync(0xffffffffu, pt[c][0], srcB);
                    uint32_t y1 = __shfl_sync(0xffffffffu, pt[c][1], srcB);
                    pa[2] = (t4 & 1) ? y1 : y0;
                    uint32_t u0 = __shfl_sync(0xffffffffu, pt[c][2], srcB);
                    uint32_t u1 = __shfl_sync(0xffffffffu, pt[c][3], srcB);
                    pa[3] = (t4 & 1) ? u1 : u0;
                }
                const int kb0 = nc0 + 8 * c;   // key rows of this chunk
                #pragma unroll
                for (int nt = 0; nt < 8; nt++) {
                    uint32_t vb[2];
                    vb[0] = __float_as_uint(sm[vOff + (kb0 + t4) * PAD + 8 * nt + g]);
                    vb[1] = __float_as_uint(sm[vOff + (kb0 + t4 + 4) * PAD + 8 * nt + g]);
                    mma8(oacc[nt], pa, vb);
                }
            }
        }

        // --- cross-warp reduction of partial O over wk, then store ---
        l0 += __shfl_xor_sync(0xffffffffu, l0, 1);
        l0 += __shfl_xor_sync(0xffffffffu, l0, 2);
        l1 += __shfl_xor_sync(0xffffffffu, l1, 1);
        l1 += __shfl_xor_sync(0xffffffffu, l1, 2);

        __syncthreads();   // all K/V reads done; RED may alias the buffers

        if (t4 == 0) {
            sm[LO + w * 16 + g]     = l0;
            sm[LO + w * 16 + g + 8] = l1;
        }
        {
            float* rw = sm + RED + w * (16 * PAD);
            #pragma unroll
            for (int nt = 0; nt < 8; nt++) {
                const int cb = 8 * nt + 2 * t4;
                *(float2*)&rw[g * PAD + cb]       = make_float2(oacc[nt][0], oacc[nt][1]);
                *(float2*)&rw[(g + 8) * PAD + cb] = make_float2(oacc[nt][2], oacc[nt][3]);
            }
        }
        __syncthreads();

        {
            const int r  = tid >> 3;            // 0..63 output row
            const int c0 = (tid & 7) * 8;       // 8 cols per thread
            const int wmr = r >> 4, ri = r & 15;
            float lt = 0.f;
            #pragma unroll
            for (int k = 0; k < 4; k++)
                lt += sm[LO + (wmr + 4 * k) * 16 + ri];
            const float inv = 1.f / lt;

            float acc8[8] = {};
            #pragma unroll
            for (int k = 0; k < 4; k++) {
                const float* rp = sm + RED + (wmr + 4 * k) * (16 * PAD) + ri * PAD + c0;
                #pragma unroll
                for (int e = 0; e < 8; e++) acc8[e] += rp[e];
            }
            float* op = g_attn + (qrow + r) * DHEAD + c0;
            #pragma unroll
            for (int e = 0; e < 8; e += 2)
                *(float2*)&op[e] = make_float2(tfr(acc8[e] * inv), tfr(acc8[e + 1] * inv));
        }
        __syncthreads();   // RED/L reads done before next pair member reloads
    }
}

// ---------------------------------------------------------------------------
// Kernel 3: tf32 tensor-core output projection (unchanged from R6).
// ---------------------------------------------------------------------------
#define AS_OFF 0
#define BS_OFF (128 * 68)
#define PROJ_SMEM ((128 * 68 + 64 * 132) * 4)

__global__ void __launch_bounds__(256) proj_tc_kernel(
    const float* __restrict__ bo, float* __restrict__ out)
{
    extern __shared__ float smp[];
    const int tid = threadIdx.x;
    const int w = tid >> 5, lane = tid & 31, g = lane >> 2, t4 = lane & 3;
    const int wm = w & 3, wn = w >> 2;
    const int rowBase = blockIdx.x * 128;
    const int nBase   = blockIdx.y * 128;
    const uint32_t smb = smem_u32(smp);

    {
        const int ar = tid >> 1, ac = (tid & 1) * 32;
        const float* ap = g_attn + (size_t)(rowBase + ar) * DHEAD + ac;
        uint32_t aa = smb + (uint32_t)(AS_OFF + ar * 68 + ac) * 4;
        #pragma unroll
        for (int i = 0; i < 8; i++) cp16(aa + 16 * i, ap + 4 * i);
        const int br = tid >> 2, bc = (tid & 3) * 32;
        const float* bp = g_wo + (size_t)br * D_MODEL + nBase + bc;
        uint32_t ba = smb + (uint32_t)(BS_OFF + br * 132 + bc) * 4;
        #pragma unroll
        for (int i = 0; i < 8; i++) cp16(ba + 16 * i, bp + 4 * i);
    }
    asm volatile("cp.async.commit_group;" ::: "memory");
    asm volatile("cp.async.wait_group 0;" ::: "memory");
    __syncthreads();

    float acc[2][8][4] = {};
    #pragma unroll
    for (int s = 0; s < 8; s++) {
        const int k0 = 8 * s;
        uint32_t af[2][4];
        #pragma unroll
        for (int i = 0; i < 2; i++) {
            const int m0 = 32 * wm + 16 * i;
            af[i][0] = __float_as_uint(smp[AS_OFF + (m0 + g) * 68 + k0 + t4]);
            af[i][1] = __float_as_uint(smp[AS_OFF + (m0 + g + 8) * 68 + k0 + t4]);
            af[i][2] = __float_as_uint(smp[AS_OFF + (m0 + g) * 68 + k0 + t4 + 4]);
            af[i][3] = __float_as_uint(smp[AS_OFF + (m0 + g + 8) * 68 + k0 + t4 + 4]);
        }
        #pragma unroll
        for (int nt = 0; nt < 8; nt++) {
            const int n0 = 64 * wn + 8 * nt;
            uint32_t bf[2];
            bf[0] = __float_as_uint(smp[BS_OFF + (k0 + t4) * 132 + n0 + g]);
            bf[1] = __float_as_uint(smp[BS_OFF + (k0 + t4 + 4) * 132 + n0 + g]);
            mma8(acc[0][nt], af[0], bf);
            mma8(acc[1][nt], af[1], bf);
        }
    }

    #pragma unroll
    for (int i = 0; i < 2; i++) {
        #pragma unroll
        for (int nt = 0; nt < 8; nt++) {
            const int col = nBase + 64 * wn + 8 * nt + 2 * t4;
            const float b0 = bo[col], b1 = bo[col + 1];
            const int rA = rowBase + 32 * wm + 16 * i + g;
            *(float2*)&out[(size_t)rA * D_MODEL + col] =
                make_float2(acc[i][nt][0] + b0, acc[i][nt][1] + b1);
            *(float2*)&out[(size_t)(rA + 8) * D_MODEL + col] =
                make_float2(acc[i][nt][2] + b0, acc[i][nt][3] + b1);
        }
    }
}

// ---------------------------------------------------------------------------
extern "C" void kernel_launch(void* const* d_in, const int* in_sizes, int n_in,
                              void* d_out, int out_size)
{
    const float* x  = (const float*)d_in[0];
    const float* Wq = (const float*)d_in[1];
    const float* bq = (const float*)d_in[2];
    const float* Wk = (const float*)d_in[3];
    const float* bk = (const float*)d_in[4];
    const float* Wv = (const float*)d_in[5];
    const float* bv = (const float*)d_in[6];
    const float* Wo = (const float*)d_in[7];
    const float* bo = (const float*)d_in[8];
    float* out = (float*)d_out;

    cudaFuncSetAttribute(qkv_tc_kernel,
                         cudaFuncAttributeMaxDynamicSharedMemorySize, QKV_SMEM);
    cudaFuncSetAttribute(attn_mma_kernel,
                         cudaFuncAttributeMaxDynamicSharedMemorySize, ATTN_SMEM);
    cudaFuncSetAttribute(proj_tc_kernel,
                         cudaFuncAttributeMaxDynamicSharedMemorySize, PROJ_SMEM);

    preround_kernel<<<2048, 256>>>((const float4*)x, (const float4*)Wq,
                                   (const float4*)Wk, (const float4*)Wv,
                                   (const float4*)Wo);
    qkv_tc_kernel<<<dim3(BSROWS / 128, 3), 256, QKV_SMEM>>>(bq, bk, bv);
    attn_mma_kernel<<<dim3(32, BATCH), 512, ATTN_SMEM>>>();
    proj_tc_kernel<<<dim3(BSROWS / 128, D_MODEL / 128), 256, PROJ_SMEM>>>(bo, out);
}